// round 11
// baseline (speedup 1.0000x reference)
#include <cuda_runtime.h>
#include <cuda_fp16.h>
#include <cstdint>

// ============================================================================
// R11 = R10 pipeline/layout verbatim, but 512 threads (16 warps, 8M x 2N,
// warp tile M16xN64): same per-CTA instruction totals, 2x warps for latency
// hiding. fp16 MMA; A fp32 smem -> LDS.64+cvt; B fp16 smem -> ldmatrix.
// ============================================================================
#define KDIM      784
#define KPAD      800
#define KCH       32
#define NCHUNK    25
#define MT        128
#define NT        128
#define NSTAGES   3
#define THREADS   512         // 16 warps: 8 in M x 2 in N, warp tile M16xN64

#define APITCH    40                        // floats (160 B rows, conflict-free)
#define A_BYTES   (MT * APITCH * 4)         // 20480
#define B_BYTES   (NT * 80)                 // 10240 (fp16, 80 B rows)
#define STAGE_BYTES (A_BYTES + B_BYTES)     // 30720
#define STAGE_F   (STAGE_BYTES / 4)
#define PH        130

// smem float offsets
#define OF_PIPE   0                         // 3*7680 = 23040 floats (92160 B)
#define OF_W2     23040                     // 1280
#define OF_B1     24320                     // 128
#define OF_B2     24448                     // 16
#define SMEM_FLOATS 24464
#define SMEM_BYTES  (SMEM_FLOATS * 4)       // 97856 -> 2 CTAs/SM
// epilogue overlays: h[128][130] = 16640 floats, then parts
#define OF_PART   16640                     // 4*128*10 = 5120
#define OF_OUTS   (OF_PART + 5120)          // 1280  (21760+1280=23040 <= fits)

__device__ __align__(16) __half g_Wt16[NT * KPAD];

// ============================================================================
// helpers
// ============================================================================
__device__ __forceinline__ uint32_t smem_u32(const void* p) {
    uint32_t a;
    asm("{ .reg .u64 t; cvta.to.shared.u64 t, %1; cvt.u32.u64 %0, t; }" : "=r"(a) : "l"(p));
    return a;
}
__device__ __forceinline__ uint32_t pack_f16x2(float lo, float hi) {
    uint32_t r;
    asm("cvt.rn.f16x2.f32 %0, %2, %1;" : "=r"(r) : "f"(lo), "f"(hi));
    return r;
}
__device__ __forceinline__ void cp_async16(uint32_t dst_smem, const void* src) {
    asm volatile("cp.async.cg.shared.global [%0], [%1], 16;" :: "r"(dst_smem), "l"(src) : "memory");
}
__device__ __forceinline__ void cp_async16_pred(uint32_t dst_smem, const void* src, int src_bytes) {
    asm volatile("cp.async.cg.shared.global [%0], [%1], 16, %2;"
                 :: "r"(dst_smem), "l"(src), "r"(src_bytes) : "memory");
}
__device__ __forceinline__ void cp_commit() { asm volatile("cp.async.commit_group;" ::: "memory"); }
__device__ __forceinline__ void cp_wait1()  { asm volatile("cp.async.wait_group 1;" ::: "memory"); }
__device__ __forceinline__ void cp_wait0()  { asm volatile("cp.async.wait_group 0;" ::: "memory"); }

__device__ __forceinline__ void ldmatrix_x4(uint32_t* r, uint32_t addr) {
    asm volatile("ldmatrix.sync.aligned.m8n8.x4.shared.b16 {%0,%1,%2,%3}, [%4];"
                 : "=r"(r[0]), "=r"(r[1]), "=r"(r[2]), "=r"(r[3]) : "r"(addr));
}
__device__ __forceinline__ void mma_f16(float* c, const uint32_t* a, uint32_t b0, uint32_t b1) {
    asm volatile("mma.sync.aligned.m16n8k16.row.col.f32.f16.f16.f32 "
                 "{%0,%1,%2,%3}, {%4,%5,%6,%7}, {%8,%9}, {%0,%1,%2,%3};"
                 : "+f"(c[0]), "+f"(c[1]), "+f"(c[2]), "+f"(c[3])
                 : "r"(a[0]), "r"(a[1]), "r"(a[2]), "r"(a[3]), "r"(b0), "r"(b1));
}

// ============================================================================
// Prep kernel: W_eff^T = (conv ⊗ w1), fp16-RN
// ============================================================================
__global__ void prep_kernel(const float* __restrict__ conv_w, const float* __restrict__ w1) {
    int idx = blockIdx.x * blockDim.x + threadIdx.x;
    if (idx >= NT * KPAD) return;
    int n = idx / KPAD;
    int k = idx - n * KPAD;
    float v = 0.f;
    if (k < KDIM) {
        int i = k / 28, j = k - (k / 28) * 28;
        #pragma unroll
        for (int dy = 0; dy < 3; ++dy) {
            int r = i - dy;
            if (r < 0 || r >= 26) continue;
            #pragma unroll
            for (int dx = 0; dx < 3; ++dx) {
                int c = j - dx;
                if (c < 0 || c >= 26) continue;
                v += conv_w[dy * 3 + dx] * w1[(r * 26 + c) * 128 + n];
            }
        }
    }
    g_Wt16[idx] = __float2half_rn(v);
}

// ============================================================================
// Main fused kernel
// ============================================================================
__global__ void __launch_bounds__(THREADS, 2)
fused_mlp_kernel(const float* __restrict__ x, const float* __restrict__ b1,
                 const float* __restrict__ w2, const float* __restrict__ b2,
                 float* __restrict__ out, int Brows) {
    extern __shared__ float sm[];
    const int tid  = threadIdx.x;
    const int wid  = tid >> 5;
    const int lane = tid & 31;
    const int tg   = lane >> 2;          // 0..7
    const int tk   = lane & 3;           // 0..3
    const int mw   = (wid >> 1) * 16;    // 8 warps in M, warp tile M16
    const int nw   = (wid & 1) * 64;     // 2 warps in N, warp tile N64
    const int m0   = blockIdx.x * MT;

    for (int i = tid; i < 1280; i += THREADS) sm[OF_W2 + i] = w2[i];
    if (tid < 128) sm[OF_B1 + tid] = b1[tid];
    if (tid < 10)  sm[OF_B2 + tid] = b2[tid];

    const uint32_t pipe_sm = smem_u32(sm + OF_PIPE);

    // ---- producer: A 2 x 16B pieces/thread (zero-fill past K=784), B 1 piece ----
    auto issue = [&](int c, int stage) {
        const uint32_t sbase = pipe_sm + (uint32_t)stage * STAGE_BYTES;
        #pragma unroll
        for (int r = 0; r < 2; ++r) {
            const int j   = tid + r * THREADS;       // 0..1023
            const int row = j >> 3, q = j & 7;
            int msrc = m0 + row; if (msrc >= Brows) msrc = Brows - 1;
            const int k0 = c * KCH + q * 4;
            cp_async16_pred(sbase + (uint32_t)(row * APITCH + q * 4) * 4,
                            x + (size_t)msrc * KDIM + k0,
                            (k0 < KDIM) ? 16 : 0);
        }
        {
            const uint32_t bbase = sbase + A_BYTES;
            const int row = tid >> 2, q = tid & 3;   // 0..127, 16B piece
            cp_async16(bbase + (uint32_t)(row * 80 + q * 16),
                       g_Wt16 + (size_t)row * KPAD + c * KCH + q * 8);
        }
    };

    float acc[8][4];
    #pragma unroll
    for (int ni = 0; ni < 8; ++ni)
        #pragma unroll
        for (int e = 0; e < 4; ++e) acc[ni][e] = 0.f;

    // B ldmatrix lane mapping (R9/R10-proven)
    const uint32_t b_lm = (uint32_t)A_BYTES
                        + (uint32_t)(nw + (lane & 7) + ((lane & 16) >> 1)) * 80
                        + (uint32_t)((lane & 8) ? 16 : 0);

    // ---- prologue ----
    issue(0, 0); cp_commit();
    issue(1, 1); cp_commit();

    // ---- mainloop (R10 structure) ----
    int stage = 0;
    for (int c = 0; c < NCHUNK; ++c) {
        cp_wait1();
        __syncthreads();

        const int cn = c + NSTAGES - 1;
        int nstage = stage + 2; if (nstage >= NSTAGES) nstage -= NSTAGES;
        if (cn < NCHUNK) issue(cn, nstage);
        cp_commit();

        const float* As = sm + OF_PIPE + stage * STAGE_F;
        const uint32_t sb = pipe_sm + (uint32_t)stage * STAGE_BYTES;

        #pragma unroll
        for (int ks = 0; ks < KCH; ks += 16) {
            // A fragment (M16): 4 LDS.64 + 4 cvt
            uint32_t a[4];
            {
                const float2* r0 = (const float2*)(As + (mw + tg) * APITCH + ks);
                const float2* r1 = (const float2*)(As + (mw + tg + 8) * APITCH + ks);
                float2 v0 = r0[tk], v1 = r1[tk], v2 = r0[tk + 4], v3 = r1[tk + 4];
                a[0] = pack_f16x2(v0.x, v0.y);
                a[1] = pack_f16x2(v1.x, v1.y);
                a[2] = pack_f16x2(v2.x, v2.y);
                a[3] = pack_f16x2(v3.x, v3.y);
            }
            // B fragments (N64): 4 ldmatrix.x4
            uint32_t b[8][2];
            #pragma unroll
            for (int g = 0; g < 4; ++g) {
                uint32_t r[4];
                ldmatrix_x4(r, sb + b_lm + (uint32_t)(g * 16 * 80 + ks * 2));
                b[2 * g][0]     = r[0]; b[2 * g][1]     = r[1];
                b[2 * g + 1][0] = r[2]; b[2 * g + 1][1] = r[3];
            }
            #pragma unroll
            for (int ni = 0; ni < 8; ++ni)
                mma_f16(acc[ni], a, b[ni][0], b[ni][1]);
        }
        ++stage; if (stage >= NSTAGES) stage = 0;
    }

    // ---- epilogue: h = relu(acc + b1) into smem overlay ----
    cp_wait0();
    __syncthreads();
    {
        float* h = sm + OF_PIPE;   // [128][PH]
        #pragma unroll
        for (int ni = 0; ni < 8; ++ni) {
            const int r = mw + tg;
            const int n = nw + ni * 8 + 2 * tk;
            const float bn0 = sm[OF_B1 + n], bn1 = sm[OF_B1 + n + 1];
            h[r * PH + n]           = fmaxf(acc[ni][0] + bn0, 0.f);
            h[r * PH + n + 1]       = fmaxf(acc[ni][1] + bn1, 0.f);
            h[(r + 8) * PH + n]     = fmaxf(acc[ni][2] + bn0, 0.f);
            h[(r + 8) * PH + n + 1] = fmaxf(acc[ni][3] + bn1, 0.f);
        }
    }
    __syncthreads();

    // ---- GEMM2: 4-way split-K (32 k each) ----
    {
        const float* h = sm + OF_PIPE;
        const int row  = tid & 127;
        const int quad = tid >> 7;            // 0..3
        float o[10];
        #pragma unroll
        for (int n = 0; n < 10; ++n) o[n] = 0.f;
        #pragma unroll 8
        for (int k = quad * 32; k < quad * 32 + 32; ++k) {
            const float t = h[row * PH + k];
            const float* wr = sm + OF_W2 + k * 10;
            #pragma unroll
            for (int n = 0; n < 10; ++n) o[n] = fmaf(t, wr[n], o[n]);
        }
        #pragma unroll
        for (int n = 0; n < 10; ++n) sm[OF_PART + (quad * 128 + row) * 10 + n] = o[n];
    }
    __syncthreads();
    if (tid < 128) {
        #pragma unroll
        for (int n = 0; n < 10; ++n)
            sm[OF_OUTS + tid * 10 + n] = sm[OF_PART + tid * 10 + n]
                                       + sm[OF_PART + (128 + tid) * 10 + n]
                                       + sm[OF_PART + (256 + tid) * 10 + n]
                                       + sm[OF_PART + (384 + tid) * 10 + n]
                                       + sm[OF_B2 + n];
    }
    __syncthreads();

    // ---- coalesced store ----
    const int nvalid = (Brows - m0 < MT) ? (Brows - m0) : MT;
    if (nvalid == MT) {
        float4* dst = (float4*)(out + (size_t)m0 * 10);
        const float4* src = (const float4*)(sm + OF_OUTS);
        if (tid < MT * 10 / 4) dst[tid] = src[tid];
    } else {
        for (int i = tid; i < nvalid * 10; i += THREADS) out[(size_t)m0 * 10 + i] = sm[OF_OUTS + i];
    }
}

// ============================================================================
// Host launch
// ============================================================================
extern "C" void kernel_launch(void* const* d_in, const int* in_sizes, int n_in,
                              void* d_out, int out_size) {
    const float* x      = (const float*)d_in[0];
    const float* conv_w = (const float*)d_in[1];
    const float* w1     = (const float*)d_in[2];
    const float* b1     = (const float*)d_in[3];
    const float* w2     = (const float*)d_in[4];
    const float* b2     = (const float*)d_in[5];
    float* out          = (float*)d_out;
    const int Brows     = in_sizes[0] / KDIM;

    static int configured = 0;
    if (!configured) {
        cudaFuncSetAttribute(fused_mlp_kernel, cudaFuncAttributeMaxDynamicSharedMemorySize, SMEM_BYTES);
        configured = 1;
    }

    prep_kernel<<<(NT * KPAD + 255) / 256, 256>>>(conv_w, w1);

    const int grid = (Brows + MT - 1) / MT;
    fused_mlp_kernel<<<grid, THREADS, SMEM_BYTES>>>(x, b1, w2, b2, out, Brows);
}

// round 12
// speedup vs baseline: 1.0627x; 1.0627x over previous
#include <cuda_runtime.h>
#include <cuda_fp16.h>
#include <cstdint>

// ============================================================================
// R12 = R10 consume path verbatim + warp-specialized producer (1 warp) with
// per-stage named-barrier handshake. 288 threads: warps 0-7 consume (4Mx2N,
// M32xN64), warp 8 produces all cp.async traffic. 3-stage ring.
// ============================================================================
#define KDIM      784
#define KPAD      800
#define KCH       32
#define NCHUNK    25
#define MT        128
#define NT        128
#define NSTAGES   3
#define THREADS   288

#define APITCH    40                        // floats (160 B rows, conflict-free)
#define A_BYTES   (MT * APITCH * 4)         // 20480
#define B_BYTES   (NT * 80)                 // 10240 (fp16, 80 B rows)
#define STAGE_BYTES (A_BYTES + B_BYTES)     // 30720
#define STAGE_F   (STAGE_BYTES / 4)
#define PH        130

// smem float offsets (identical to R10)
#define OF_PIPE   0                         // 3*7680 = 23040 floats (92160 B)
#define OF_W2     23040
#define OF_B1     24320
#define OF_B2     24448
#define SMEM_FLOATS 24464
#define SMEM_BYTES  (SMEM_FLOATS * 4)       // 97856 -> 2 CTAs/SM
#define OF_PART   16640
#define OF_OUTS   19200

__device__ __align__(16) __half g_Wt16[NT * KPAD];

// ============================================================================
// helpers (baseline PTX only)
// ============================================================================
__device__ __forceinline__ uint32_t smem_u32(const void* p) {
    uint32_t a;
    asm("{ .reg .u64 t; cvta.to.shared.u64 t, %1; cvt.u32.u64 %0, t; }" : "=r"(a) : "l"(p));
    return a;
}
__device__ __forceinline__ uint32_t pack_f16x2(float lo, float hi) {
    uint32_t r;
    asm("cvt.rn.f16x2.f32 %0, %2, %1;" : "=r"(r) : "f"(lo), "f"(hi));
    return r;
}
__device__ __forceinline__ void cp_async16(uint32_t dst_smem, const void* src) {
    asm volatile("cp.async.cg.shared.global [%0], [%1], 16;" :: "r"(dst_smem), "l"(src) : "memory");
}
__device__ __forceinline__ void cp_async16_pred(uint32_t dst_smem, const void* src, int src_bytes) {
    asm volatile("cp.async.cg.shared.global [%0], [%1], 16, %2;"
                 :: "r"(dst_smem), "l"(src), "r"(src_bytes) : "memory");
}
__device__ __forceinline__ void cp_commit() { asm volatile("cp.async.commit_group;" ::: "memory"); }
__device__ __forceinline__ void cp_wait1()  { asm volatile("cp.async.wait_group 1;" ::: "memory"); }
__device__ __forceinline__ void cp_wait0()  { asm volatile("cp.async.wait_group 0;" ::: "memory"); }

__device__ __forceinline__ void bar_sync_n(int id) {
    asm volatile("bar.sync %0, %1;" :: "r"(id), "r"(THREADS) : "memory");
}
__device__ __forceinline__ void bar_arrive_n(int id) {
    asm volatile("bar.arrive %0, %1;" :: "r"(id), "r"(THREADS) : "memory");
}

__device__ __forceinline__ void ldmatrix_x4(uint32_t* r, uint32_t addr) {
    asm volatile("ldmatrix.sync.aligned.m8n8.x4.shared.b16 {%0,%1,%2,%3}, [%4];"
                 : "=r"(r[0]), "=r"(r[1]), "=r"(r[2]), "=r"(r[3]) : "r"(addr));
}
__device__ __forceinline__ void mma_f16(float* c, const uint32_t* a, uint32_t b0, uint32_t b1) {
    asm volatile("mma.sync.aligned.m16n8k16.row.col.f32.f16.f16.f32 "
                 "{%0,%1,%2,%3}, {%4,%5,%6,%7}, {%8,%9}, {%0,%1,%2,%3};"
                 : "+f"(c[0]), "+f"(c[1]), "+f"(c[2]), "+f"(c[3])
                 : "r"(a[0]), "r"(a[1]), "r"(a[2]), "r"(a[3]), "r"(b0), "r"(b1));
}

// ============================================================================
// Prep kernel: W_eff^T = (conv ⊗ w1), fp16-RN
// ============================================================================
__global__ void prep_kernel(const float* __restrict__ conv_w, const float* __restrict__ w1) {
    int idx = blockIdx.x * blockDim.x + threadIdx.x;
    if (idx >= NT * KPAD) return;
    int n = idx / KPAD;
    int k = idx - n * KPAD;
    float v = 0.f;
    if (k < KDIM) {
        int i = k / 28, j = k - (k / 28) * 28;
        #pragma unroll
        for (int dy = 0; dy < 3; ++dy) {
            int r = i - dy;
            if (r < 0 || r >= 26) continue;
            #pragma unroll
            for (int dx = 0; dx < 3; ++dx) {
                int c = j - dx;
                if (c < 0 || c >= 26) continue;
                v += conv_w[dy * 3 + dx] * w1[(r * 26 + c) * 128 + n];
            }
        }
    }
    g_Wt16[idx] = __float2half_rn(v);
}

// ============================================================================
// Main fused kernel
// ============================================================================
__global__ void __launch_bounds__(THREADS, 2)
fused_mlp_kernel(const float* __restrict__ x, const float* __restrict__ b1,
                 const float* __restrict__ w2, const float* __restrict__ b2,
                 float* __restrict__ out, int Brows) {
    extern __shared__ float sm[];
    const int tid  = threadIdx.x;
    const int wid  = tid >> 5;
    const int lane = tid & 31;
    const int tg   = lane >> 2;
    const int tk   = lane & 3;
    const int m0   = blockIdx.x * MT;

    for (int i = tid; i < 1280; i += THREADS) sm[OF_W2 + i] = w2[i];
    if (tid < 128) sm[OF_B1 + tid] = b1[tid];
    if (tid < 10)  sm[OF_B2 + tid] = b2[tid];

    const uint32_t pipe_sm = smem_u32(sm + OF_PIPE);

    if (wid == 8) {
        // ================= PRODUCER WARP =================
        const int ptid = lane;     // 0..31
        auto p_issue = [&](int c, int stage) {
            const uint32_t sbase = pipe_sm + (uint32_t)stage * STAGE_BYTES;
            #pragma unroll
            for (int r = 0; r < 32; ++r) {            // A: 1024 x 16B pieces
                const int j   = ptid + r * 32;
                const int row = j >> 3, q = j & 7;
                int msrc = m0 + row; if (msrc >= Brows) msrc = Brows - 1;
                const int k0 = c * KCH + q * 4;
                cp_async16_pred(sbase + (uint32_t)(row * APITCH + q * 4) * 4,
                                x + (size_t)msrc * KDIM + k0,
                                (k0 < KDIM) ? 16 : 0);
            }
            const uint32_t bbase = sbase + A_BYTES;
            #pragma unroll
            for (int r = 0; r < 20; ++r) {            // B: 640 x 16B pieces
                const int j   = ptid + r * 32;
                const int row = j / 5, q = j - row * 5;
                cp_async16(bbase + (uint32_t)(row * 80 + q * 16),
                           g_Wt16 + (size_t)row * KPAD + c * KCH + q * 8);
            }
        };

        p_issue(0, 0); cp_commit();
        p_issue(1, 1); cp_commit();
        for (int c = 0; c < NCHUNK; ++c) {
            cp_wait1();                    // groups committed = 2+c; chunk c == group c done
            bar_arrive_n(1 + c % 3);       // full[c%3]: stage ready
            const int n = c + 2;
            if (n < NCHUNK) {
                if (n >= NSTAGES) bar_sync_n(4 + n % 3);   // empty[n%3]: consumers freed it
                p_issue(n, n % 3);
            }
            cp_commit();                   // always commit (keeps group arithmetic uniform)
        }
        cp_wait0();
    } else {
        // ================= CONSUMER WARPS (R10 consume verbatim) =================
        const int mw = (wid >> 1) * 32;    // 4 warps in M
        const int nw = (wid & 1) * 64;     // 2 warps in N

        float acc[2][8][4];
        #pragma unroll
        for (int mi = 0; mi < 2; ++mi)
            #pragma unroll
            for (int ni = 0; ni < 8; ++ni)
                #pragma unroll
                for (int e = 0; e < 4; ++e) acc[mi][ni][e] = 0.f;

        const uint32_t b_lm = (uint32_t)A_BYTES
                            + (uint32_t)(nw + (lane & 7) + ((lane & 16) >> 1)) * 80
                            + (uint32_t)((lane & 8) ? 16 : 0);

        for (int c = 0; c < NCHUNK; ++c) {
            const int s = c % 3;
            bar_sync_n(1 + s);             // wait stage full (satisfied early in steady state)

            const float* As = sm + OF_PIPE + s * STAGE_F;
            const uint32_t sb = pipe_sm + (uint32_t)s * STAGE_BYTES;

            #pragma unroll
            for (int ks = 0; ks < KCH; ks += 16) {
                uint32_t a[2][4];
                #pragma unroll
                for (int mi = 0; mi < 2; ++mi) {
                    const float2* r0 = (const float2*)(As + (mw + mi * 16 + tg) * APITCH + ks);
                    const float2* r1 = (const float2*)(As + (mw + mi * 16 + tg + 8) * APITCH + ks);
                    float2 v0 = r0[tk], v1 = r1[tk], v2 = r0[tk + 4], v3 = r1[tk + 4];
                    a[mi][0] = pack_f16x2(v0.x, v0.y);
                    a[mi][1] = pack_f16x2(v1.x, v1.y);
                    a[mi][2] = pack_f16x2(v2.x, v2.y);
                    a[mi][3] = pack_f16x2(v3.x, v3.y);
                }
                uint32_t b[8][2];
                #pragma unroll
                for (int g = 0; g < 4; ++g) {
                    uint32_t r[4];
                    ldmatrix_x4(r, sb + b_lm + (uint32_t)(g * 16 * 80 + ks * 2));
                    b[2 * g][0]     = r[0]; b[2 * g][1]     = r[1];
                    b[2 * g + 1][0] = r[2]; b[2 * g + 1][1] = r[3];
                }
                #pragma unroll
                for (int mi = 0; mi < 2; ++mi)
                    #pragma unroll
                    for (int ni = 0; ni < 8; ++ni)
                        mma_f16(acc[mi][ni], a[mi], b[ni][0], b[ni][1]);
            }

            if (c + NSTAGES < NCHUNK) bar_arrive_n(4 + s);   // empty[s]: stage reusable
        }

        // stash accumulators into h AFTER the global sync below (needs all consumers done
        // reading pipe region -- the __syncthreads covers it); write happens post-sync.
        __syncthreads();
        {
            float* h = sm + OF_PIPE;   // [128][PH] overlay
            #pragma unroll
            for (int mi = 0; mi < 2; ++mi) {
                #pragma unroll
                for (int ni = 0; ni < 8; ++ni) {
                    const int r = mw + mi * 16 + tg;
                    const int n = nw + ni * 8 + 2 * tk;
                    const float bn0 = sm[OF_B1 + n], bn1 = sm[OF_B1 + n + 1];
                    h[r * PH + n]           = fmaxf(acc[mi][ni][0] + bn0, 0.f);
                    h[r * PH + n + 1]       = fmaxf(acc[mi][ni][1] + bn1, 0.f);
                    h[(r + 8) * PH + n]     = fmaxf(acc[mi][ni][2] + bn0, 0.f);
                    h[(r + 8) * PH + n + 1] = fmaxf(acc[mi][ni][3] + bn1, 0.f);
                }
            }
        }
    }

    // producer joins the consumer __syncthreads above / consumers' h-write sync below
    if (wid == 8) __syncthreads();   // pairs with consumers' first __syncthreads
    __syncthreads();                 // h fully written

    // ---- GEMM2: split-K over 2 threads/row (256 threads) ----
    if (tid < 256) {
        const float* h = sm + OF_PIPE;
        const int row  = tid & 127;
        const int half = tid >> 7;
        float o[10];
        #pragma unroll
        for (int n = 0; n < 10; ++n) o[n] = 0.f;
        #pragma unroll 8
        for (int k = half * 64; k < half * 64 + 64; ++k) {
            const float t = h[row * PH + k];
            const float* wr = sm + OF_W2 + k * 10;
            #pragma unroll
            for (int n = 0; n < 10; ++n) o[n] = fmaf(t, wr[n], o[n]);
        }
        #pragma unroll
        for (int n = 0; n < 10; ++n) sm[OF_PART + tid * 10 + n] = o[n];
    }
    __syncthreads();
    if (tid < 128) {
        #pragma unroll
        for (int n = 0; n < 10; ++n)
            sm[OF_OUTS + tid * 10 + n] = sm[OF_PART + tid * 10 + n]
                                       + sm[OF_PART + (tid + 128) * 10 + n]
                                       + sm[OF_B2 + n];
    }
    __syncthreads();

    // ---- coalesced store ----
    const int nvalid = (Brows - m0 < MT) ? (Brows - m0) : MT;
    if (nvalid == MT) {
        float4* dst = (float4*)(out + (size_t)m0 * 10);
        const float4* src = (const float4*)(sm + OF_OUTS);
        for (int i = tid; i < MT * 10 / 4; i += THREADS) dst[i] = src[i];
    } else {
        for (int i = tid; i < nvalid * 10; i += THREADS) out[(size_t)m0 * 10 + i] = sm[OF_OUTS + i];
    }
}

// ============================================================================
// Host launch
// ============================================================================
extern "C" void kernel_launch(void* const* d_in, const int* in_sizes, int n_in,
                              void* d_out, int out_size) {
    const float* x      = (const float*)d_in[0];
    const float* conv_w = (const float*)d_in[1];
    const float* w1     = (const float*)d_in[2];
    const float* b1     = (const float*)d_in[3];
    const float* w2     = (const float*)d_in[4];
    const float* b2     = (const float*)d_in[5];
    float* out          = (float*)d_out;
    const int Brows     = in_sizes[0] / KDIM;

    static int configured = 0;
    if (!configured) {
        cudaFuncSetAttribute(fused_mlp_kernel, cudaFuncAttributeMaxDynamicSharedMemorySize, SMEM_BYTES);
        configured = 1;
    }

    prep_kernel<<<(NT * KPAD + 255) / 256, 256>>>(conv_w, w1);

    const int grid = (Brows + MT - 1) / MT;
    fused_mlp_kernel<<<grid, THREADS, SMEM_BYTES>>>(x, b1, w2, b2, out, Brows);
}

// round 13
// speedup vs baseline: 1.0724x; 1.0091x over previous
#include <cuda_runtime.h>
#include <cuda_fp16.h>
#include <cstdint>

// ============================================================================
// R13 = R10 per-warp code verbatim, CTA tile doubled to M256xN128 (512 thr,
// 16 warps = 8M x 2N of warp tile M32xN64), 1 CTA/SM. Amortizes the fixed
// per-rendezvous overhead over 2x work; halves B L2 traffic.
// ============================================================================
#define KDIM      784
#define KPAD      800
#define KCH       32
#define NCHUNK    25
#define MT        256
#define NT        128
#define NSTAGES   3
#define THREADS   512

#define APITCH    40                        // floats (160 B rows, conflict-free)
#define A_BYTES   (MT * APITCH * 4)         // 40960
#define B_BYTES   (NT * 80)                 // 10240 (fp16, 80 B rows)
#define STAGE_BYTES (A_BYTES + B_BYTES)     // 51200
#define STAGE_F   (STAGE_BYTES / 4)         // 12800
#define PH        130

// smem float offsets
#define OF_PIPE   0                         // 3*12800 = 38400 floats (153600 B)
#define OF_W2     38400                     // 1280
#define OF_B1     39680                     // 128
#define OF_B2     39808                     // 16
#define SMEM_FLOATS 39824
#define SMEM_BYTES  (SMEM_FLOATS * 4)       // 159296 -> 1 CTA/SM
// epilogue overlays inside pipe region: h[256][130] = 33280 floats
#define OF_PART   33280                     // 512*10 = 5120 (33280+5120=38400 fits)

__device__ __align__(16) __half g_Wt16[NT * KPAD];

// ============================================================================
// helpers (baseline PTX only)
// ============================================================================
__device__ __forceinline__ uint32_t smem_u32(const void* p) {
    uint32_t a;
    asm("{ .reg .u64 t; cvta.to.shared.u64 t, %1; cvt.u32.u64 %0, t; }" : "=r"(a) : "l"(p));
    return a;
}
__device__ __forceinline__ uint32_t pack_f16x2(float lo, float hi) {
    uint32_t r;
    asm("cvt.rn.f16x2.f32 %0, %2, %1;" : "=r"(r) : "f"(lo), "f"(hi));
    return r;
}
__device__ __forceinline__ void cp_async16(uint32_t dst_smem, const void* src) {
    asm volatile("cp.async.cg.shared.global [%0], [%1], 16;" :: "r"(dst_smem), "l"(src) : "memory");
}
__device__ __forceinline__ void cp_async16_pred(uint32_t dst_smem, const void* src, int src_bytes) {
    asm volatile("cp.async.cg.shared.global [%0], [%1], 16, %2;"
                 :: "r"(dst_smem), "l"(src), "r"(src_bytes) : "memory");
}
__device__ __forceinline__ void cp_commit() { asm volatile("cp.async.commit_group;" ::: "memory"); }
__device__ __forceinline__ void cp_wait1()  { asm volatile("cp.async.wait_group 1;" ::: "memory"); }
__device__ __forceinline__ void cp_wait0()  { asm volatile("cp.async.wait_group 0;" ::: "memory"); }

__device__ __forceinline__ void ldmatrix_x4(uint32_t* r, uint32_t addr) {
    asm volatile("ldmatrix.sync.aligned.m8n8.x4.shared.b16 {%0,%1,%2,%3}, [%4];"
                 : "=r"(r[0]), "=r"(r[1]), "=r"(r[2]), "=r"(r[3]) : "r"(addr));
}
__device__ __forceinline__ void mma_f16(float* c, const uint32_t* a, uint32_t b0, uint32_t b1) {
    asm volatile("mma.sync.aligned.m16n8k16.row.col.f32.f16.f16.f32 "
                 "{%0,%1,%2,%3}, {%4,%5,%6,%7}, {%8,%9}, {%0,%1,%2,%3};"
                 : "+f"(c[0]), "+f"(c[1]), "+f"(c[2]), "+f"(c[3])
                 : "r"(a[0]), "r"(a[1]), "r"(a[2]), "r"(a[3]), "r"(b0), "r"(b1));
}

// ============================================================================
// Prep kernel: W_eff^T = (conv ⊗ w1), fp16-RN
// ============================================================================
__global__ void prep_kernel(const float* __restrict__ conv_w, const float* __restrict__ w1) {
    int idx = blockIdx.x * blockDim.x + threadIdx.x;
    if (idx >= NT * KPAD) return;
    int n = idx / KPAD;
    int k = idx - n * KPAD;
    float v = 0.f;
    if (k < KDIM) {
        int i = k / 28, j = k - (k / 28) * 28;
        #pragma unroll
        for (int dy = 0; dy < 3; ++dy) {
            int r = i - dy;
            if (r < 0 || r >= 26) continue;
            #pragma unroll
            for (int dx = 0; dx < 3; ++dx) {
                int c = j - dx;
                if (c < 0 || c >= 26) continue;
                v += conv_w[dy * 3 + dx] * w1[(r * 26 + c) * 128 + n];
            }
        }
    }
    g_Wt16[idx] = __float2half_rn(v);
}

// ============================================================================
// Main fused kernel: out = relu(x @ W_eff + b1) @ w2 + b2
// ============================================================================
__global__ void __launch_bounds__(THREADS, 1)
fused_mlp_kernel(const float* __restrict__ x, const float* __restrict__ b1,
                 const float* __restrict__ w2, const float* __restrict__ b2,
                 float* __restrict__ out, int Brows) {
    extern __shared__ float sm[];
    const int tid  = threadIdx.x;
    const int wid  = tid >> 5;
    const int lane = tid & 31;
    const int tg   = lane >> 2;          // 0..7
    const int tk   = lane & 3;           // 0..3
    const int mw   = (wid >> 1) * 32;    // 8 warps in M -> rows 0..255
    const int nw   = (wid & 1) * 64;     // 2 warps in N
    const int m0   = blockIdx.x * MT;

    for (int i = tid; i < 1280; i += THREADS) sm[OF_W2 + i] = w2[i];
    if (tid < 128) sm[OF_B1 + tid] = b1[tid];
    if (tid < 10)  sm[OF_B2 + tid] = b2[tid];

    const uint32_t pipe_sm = smem_u32(sm + OF_PIPE);

    // ---- producer: A 4 x 16B pieces/thread (2048 total), B 640 pieces ----
    auto issue = [&](int c, int stage) {
        const uint32_t sbase = pipe_sm + (uint32_t)stage * STAGE_BYTES;
        #pragma unroll
        for (int r = 0; r < 4; ++r) {
            const int j   = tid + r * THREADS;       // 0..2047
            const int row = j >> 3, q = j & 7;       // row 0..255, 16B piece
            int msrc = m0 + row; if (msrc >= Brows) msrc = Brows - 1;
            const int k0 = c * KCH + q * 4;
            cp_async16_pred(sbase + (uint32_t)(row * APITCH + q * 4) * 4,
                            x + (size_t)msrc * KDIM + k0,
                            (k0 < KDIM) ? 16 : 0);
        }
        const uint32_t bbase = sbase + A_BYTES;
        {   // pieces 0..511
            const int row = tid / 5, q = tid - (tid / 5) * 5;
            if (row < 128)
                cp_async16(bbase + (uint32_t)(row * 80 + q * 16),
                           g_Wt16 + (size_t)row * KPAD + c * KCH + q * 8);
        }
        {   // pieces 512..639
            const int j = tid + THREADS;
            if (j < 640) {
                const int row = j / 5, q = j - (j / 5) * 5;
                cp_async16(bbase + (uint32_t)(row * 80 + q * 16),
                           g_Wt16 + (size_t)row * KPAD + c * KCH + q * 8);
            }
        }
    };

    float acc[2][8][4];
    #pragma unroll
    for (int mi = 0; mi < 2; ++mi)
        #pragma unroll
        for (int ni = 0; ni < 8; ++ni)
            #pragma unroll
            for (int e = 0; e < 4; ++e) acc[mi][ni][e] = 0.f;

    // B ldmatrix lane mapping (R9/R10-proven)
    const uint32_t b_lm = (uint32_t)A_BYTES
                        + (uint32_t)(nw + (lane & 7) + ((lane & 16) >> 1)) * 80
                        + (uint32_t)((lane & 8) ? 16 : 0);

    // ---- prologue ----
    issue(0, 0); cp_commit();
    issue(1, 1); cp_commit();

    // ---- mainloop (R10 structure verbatim) ----
    int stage = 0;
    for (int c = 0; c < NCHUNK; ++c) {
        cp_wait1();
        __syncthreads();

        const int cn = c + NSTAGES - 1;
        int nstage = stage + 2; if (nstage >= NSTAGES) nstage -= NSTAGES;
        if (cn < NCHUNK) issue(cn, nstage);
        cp_commit();

        const float* As = sm + OF_PIPE + stage * STAGE_F;
        const uint32_t sb = pipe_sm + (uint32_t)stage * STAGE_BYTES;

        #pragma unroll
        for (int ks = 0; ks < KCH; ks += 16) {
            uint32_t a[2][4];
            #pragma unroll
            for (int mi = 0; mi < 2; ++mi) {
                const float2* r0 = (const float2*)(As + (mw + mi * 16 + tg) * APITCH + ks);
                const float2* r1 = (const float2*)(As + (mw + mi * 16 + tg + 8) * APITCH + ks);
                float2 v0 = r0[tk], v1 = r1[tk], v2 = r0[tk + 4], v3 = r1[tk + 4];
                a[mi][0] = pack_f16x2(v0.x, v0.y);
                a[mi][1] = pack_f16x2(v1.x, v1.y);
                a[mi][2] = pack_f16x2(v2.x, v2.y);
                a[mi][3] = pack_f16x2(v3.x, v3.y);
            }
            uint32_t b[8][2];
            #pragma unroll
            for (int g = 0; g < 4; ++g) {
                uint32_t r[4];
                ldmatrix_x4(r, sb + b_lm + (uint32_t)(g * 16 * 80 + ks * 2));
                b[2 * g][0]     = r[0]; b[2 * g][1]     = r[1];
                b[2 * g + 1][0] = r[2]; b[2 * g + 1][1] = r[3];
            }
            #pragma unroll
            for (int mi = 0; mi < 2; ++mi)
                #pragma unroll
                for (int ni = 0; ni < 8; ++ni)
                    mma_f16(acc[mi][ni], a[mi], b[ni][0], b[ni][1]);
        }
        ++stage; if (stage >= NSTAGES) stage = 0;
    }

    // ---- epilogue: h = relu(acc + b1) into smem overlay ----
    cp_wait0();
    __syncthreads();
    {
        float* h = sm + OF_PIPE;   // [256][PH]
        #pragma unroll
        for (int mi = 0; mi < 2; ++mi) {
            #pragma unroll
            for (int ni = 0; ni < 8; ++ni) {
                const int r = mw + mi * 16 + tg;
                const int n = nw + ni * 8 + 2 * tk;
                const float bn0 = sm[OF_B1 + n], bn1 = sm[OF_B1 + n + 1];
                h[r * PH + n]           = fmaxf(acc[mi][ni][0] + bn0, 0.f);
                h[r * PH + n + 1]       = fmaxf(acc[mi][ni][1] + bn1, 0.f);
                h[(r + 8) * PH + n]     = fmaxf(acc[mi][ni][2] + bn0, 0.f);
                h[(r + 8) * PH + n + 1] = fmaxf(acc[mi][ni][3] + bn1, 0.f);
            }
        }
    }
    __syncthreads();

    // ---- GEMM2: split-K over 2 threads/row (512 threads, 256 rows) ----
    {
        const float* h = sm + OF_PIPE;
        const int row  = tid & 255;
        const int half = tid >> 8;
        float o[10];
        #pragma unroll
        for (int n = 0; n < 10; ++n) o[n] = 0.f;
        #pragma unroll 8
        for (int k = half * 64; k < half * 64 + 64; ++k) {
            const float t = h[row * PH + k];
            const float* wr = sm + OF_W2 + k * 10;
            #pragma unroll
            for (int n = 0; n < 10; ++n) o[n] = fmaf(t, wr[n], o[n]);
        }
        #pragma unroll
        for (int n = 0; n < 10; ++n) sm[OF_PART + tid * 10 + n] = o[n];
    }
    __syncthreads();

    // final reduce into registers, then overlay-stage for coalesced store
    float o[10];
    if (tid < 256) {
        #pragma unroll
        for (int n = 0; n < 10; ++n)
            o[n] = sm[OF_PART + tid * 10 + n] + sm[OF_PART + (tid + 256) * 10 + n] + sm[OF_B2 + n];
    }
    __syncthreads();
    if (tid < 256) {
        #pragma unroll
        for (int n = 0; n < 10; ++n) sm[OF_PART + tid * 10 + n] = o[n];
    }
    __syncthreads();

    const int nvalid = (Brows - m0 < MT) ? (Brows - m0) : MT;
    if (nvalid == MT) {
        float4* dst = (float4*)(out + (size_t)m0 * 10);
        const float4* src = (const float4*)(sm + OF_PART);
        for (int i = tid; i < MT * 10 / 4; i += THREADS) dst[i] = src[i];
    } else {
        for (int i = tid; i < nvalid * 10; i += THREADS) out[(size_t)m0 * 10 + i] = sm[OF_PART + i];
    }
}

// ============================================================================
// Host launch
// ============================================================================
extern "C" void kernel_launch(void* const* d_in, const int* in_sizes, int n_in,
                              void* d_out, int out_size) {
    const float* x      = (const float*)d_in[0];
    const float* conv_w = (const float*)d_in[1];
    const float* w1     = (const float*)d_in[2];
    const float* b1     = (const float*)d_in[3];
    const float* w2     = (const float*)d_in[4];
    const float* b2     = (const float*)d_in[5];
    float* out          = (float*)d_out;
    const int Brows     = in_sizes[0] / KDIM;

    static int configured = 0;
    if (!configured) {
        cudaFuncSetAttribute(fused_mlp_kernel, cudaFuncAttributeMaxDynamicSharedMemorySize, SMEM_BYTES);
        configured = 1;
    }

    prep_kernel<<<(NT * KPAD + 255) / 256, 256>>>(conv_w, w1);

    const int grid = (Brows + MT - 1) / MT;
    fused_mlp_kernel<<<grid, THREADS, SMEM_BYTES>>>(x, b1, w2, b2, out, Brows);
}